// round 11
// baseline (speedup 1.0000x reference)
#include <cuda_runtime.h>
#include <math.h>
#include <stdint.h>

#define D      1024
#define L      128
#define NB     16      // number of segments (B)
#define NC     256     // logit columns: 128 (a) + 128 (b)
#define BM     128     // rows per GEMM block tile
#define KC     32      // K-chunk (floats)
#define NK     (D / KC)        // 32
#define STAGES 3
#define NMAX   131072
#define FBM    64      // rows per block in k_final
#define EPI_S  132     // epilogue smem stride

// ---------------- device scratch (no allocations allowed) ----------------
__device__ float    g_segsum[NB];
__device__ int      g_is64;
__device__ int      g_batch32[NMAX];

__device__ __forceinline__ uint32_t smem_u32(const void* p) {
    return (uint32_t)__cvta_generic_to_shared(p);
}
__device__ __forceinline__ void cp16(uint32_t dst, const void* src, int sz) {
    asm volatile("cp.async.cg.shared.global [%0], [%1], 16, %2;"
                 :: "r"(dst), "l"(src), "r"(sz));
}
__device__ __forceinline__ void mma_tf32(float* c, const uint32_t* a,
                                         uint32_t b0, uint32_t b1) {
    asm volatile("mma.sync.aligned.m16n8k8.row.col.f32.tf32.tf32.f32 "
                 "{%0,%1,%2,%3}, {%4,%5,%6,%7}, {%8,%9}, {%0,%1,%2,%3};"
                 : "+f"(c[0]), "+f"(c[1]), "+f"(c[2]), "+f"(c[3])
                 : "r"(a[0]), "r"(a[1]), "r"(a[2]), "r"(a[3]),
                   "r"(b0), "r"(b1));
}
// XOR-chunk swizzle for 32-float rows: phys = r*32 + ((k/4 ^ (r&7))*4) + k%4
__device__ __forceinline__ int swz(int r, int k) {
    return r * KC + ((((k >> 2) ^ (r & 7)) & 7) << 2) + (k & 3);
}

// ---------------- batch dtype detection + canonicalization ---------------
__global__ void k_detect(const unsigned* __restrict__ words, int n) {
    __shared__ int zeros;
    if (threadIdx.x == 0) zeros = 0;
    __syncthreads();
    int start = (n > 128) ? (n - 128) : 0;
    for (int j = start + threadIdx.x; j < n; j += blockDim.x)
        if ((j & 1) && words[j] == 0u) atomicAdd(&zeros, 1);
    __syncthreads();
    if (threadIdx.x == 0) g_is64 = (zeros > 32) ? 1 : 0;
}
__global__ void k_convert(const void* __restrict__ b, int n) {
    int i = blockIdx.x * blockDim.x + threadIdx.x;
    if (i >= n) return;
    if (g_is64) g_batch32[i] = (int)((const long long*)b)[i];
    else        g_batch32[i] = ((const int*)b)[i];
}
__global__ void k_init(float* __restrict__ out_acc) {
    int i = blockIdx.x * blockDim.x + threadIdx.x;
    int stride = gridDim.x * blockDim.x;
    for (int j = i; j < NB * D; j += stride) out_acc[j] = 0.0f;
    if (i < NB) g_segsum[i] = 0.0f;
}

// ---------------- TF32 tensor-core GEMM + fused epilogue -------------------
// block tile: 128 rows x 256 cols, 512 threads, warp grid 4(m) x 4(n),
// warp tile 32x64. 3-stage cp.async pipeline, KC=32 (R4-measured config).
// Epilogue additionally accumulates per-segment sum of exp(score) into
// g_segsum (unshifted softmax; |score| <= sum|Wc| ~ 13, well inside fp32).
__global__ __launch_bounds__(512, 1)
void k_gemm_mma(const float* __restrict__ feat,
                const float* __restrict__ Wa, const float* __restrict__ ba,
                const float* __restrict__ Wb, const float* __restrict__ bb,
                const float* __restrict__ Wc, const float* __restrict__ bc,
                float* __restrict__ score, int n)
{
    extern __shared__ float sm[];
    float* As_base = sm;                           // [STAGES][BM*KC]
    float* Bs_base = sm + STAGES * BM * KC;        // [STAGES][NC*KC]
    float* a_act   = sm;                           // epilogue reuse [BM][EPI_S]
    float* score_s = sm + BM * EPI_S;              // [BM][2]
    __shared__ float seg_part[NB];

    const int t      = threadIdx.x;
    const int lane   = t & 31;
    const int wid    = t >> 5;
    const int g      = lane >> 2;
    const int tg     = lane & 3;
    const int warp_m = (wid & 3) * 32;
    const int warp_n = (wid >> 2) * 64;
    const int r0     = blockIdx.x * BM;

    float cacc[2][8][4];
#pragma unroll
    for (int i = 0; i < 2; i++)
#pragma unroll
        for (int j = 0; j < 8; j++)
#pragma unroll
            for (int q = 0; q < 4; q++) cacc[i][j][q] = 0.0f;

    // -------- loader precompute (8 threads cover one 32-float row) ---------
    uint32_t a_dst[2]; const float* a_src[2]; int a_sz[2];
#pragma unroll
    for (int i = 0; i < 2; i++) {
        int id = t + 512 * i;
        int ar = id >> 3, ac = id & 7;
        int row = r0 + ar;
        int safe = (row < n) ? row : (n - 1);
        a_src[i] = feat + (size_t)safe * D + 4 * ac;
        a_sz[i]  = (row < n) ? 16 : 0;
        a_dst[i] = smem_u32(As_base + ar * KC + (((ac ^ (ar & 7)) & 7) << 2));
    }
    uint32_t b_dst[4]; const float* b_src[4];
#pragma unroll
    for (int i = 0; i < 4; i++) {
        int id = t + 512 * i;
        int nr = id >> 3, c = id & 7;
        b_src[i] = ((nr < L) ? (Wa + (size_t)nr * D)
                             : (Wb + (size_t)(nr - L) * D)) + 4 * c;
        b_dst[i] = smem_u32(Bs_base + nr * KC + (((c ^ (nr & 7)) & 7) << 2));
    }

    auto load_stage = [&](int slot, int kc) {
        uint32_t soA = (uint32_t)(slot * BM * KC * 4);
        uint32_t soB = (uint32_t)(slot * NC * KC * 4);
#pragma unroll
        for (int i = 0; i < 2; i++) cp16(a_dst[i] + soA, a_src[i] + kc, a_sz[i]);
#pragma unroll
        for (int i = 0; i < 4; i++) cp16(b_dst[i] + soB, b_src[i] + kc, 16);
    };

    auto compute_stage = [&](int slot) {
        const float* As = As_base + slot * (BM * KC);
        const float* Bs = Bs_base + slot * (NC * KC);
#pragma unroll
        for (int ks = 0; ks < 4; ks++) {
            const int k0 = 8 * ks;
            uint32_t af[2][4];
#pragma unroll
            for (int mi = 0; mi < 2; mi++) {
                int r1 = warp_m + 16 * mi + g;
                af[mi][0] = __float_as_uint(As[swz(r1,     k0 + tg)]);
                af[mi][1] = __float_as_uint(As[swz(r1 + 8, k0 + tg)]);
                af[mi][2] = __float_as_uint(As[swz(r1,     k0 + 4 + tg)]);
                af[mi][3] = __float_as_uint(As[swz(r1 + 8, k0 + 4 + tg)]);
            }
#pragma unroll
            for (int nj = 0; nj < 8; nj++) {
                int nr = warp_n + 8 * nj + g;
                uint32_t b0 = __float_as_uint(Bs[swz(nr, k0 + tg)]);
                uint32_t b1 = __float_as_uint(Bs[swz(nr, k0 + 4 + tg)]);
                mma_tf32(cacc[0][nj], af[0], b0, b1);
                mma_tf32(cacc[1][nj], af[1], b0, b1);
            }
        }
    };

    // -------- 3-stage pipeline --------
#pragma unroll
    for (int s = 0; s < STAGES - 1; s++) {
        load_stage(s, s * KC);
        asm volatile("cp.async.commit_group;" ::: "memory");
    }
    for (int ki = 0; ki < NK; ki++) {
        asm volatile("cp.async.wait_group 1;" ::: "memory");
        __syncthreads();                       // data ki visible; ki-1 compute done
        int kn = ki + STAGES - 1;
        if (kn < NK) load_stage(kn % STAGES, kn * KC);
        asm volatile("cp.async.commit_group;" ::: "memory");
        compute_stage(ki % STAGES);
    }
    asm volatile("cp.async.wait_group 0;" ::: "memory");
    __syncthreads();   // all compute done; smem now reusable for epilogue

    // -------- epilogue phase 1: a-warps stage Wc*sigmoid into smem ----------
    const bool is_a = (warp_n < L);
    if (is_a) {
#pragma unroll
        for (int nj = 0; nj < 8; nj++) {
            int c0 = warp_n + 8 * nj + 2 * tg;
            float p0 = ba[c0], p1 = ba[c0 + 1];
            float q0 = Wc[c0], q1 = Wc[c0 + 1];
#pragma unroll
            for (int mi = 0; mi < 2; mi++) {
                int r1 = warp_m + 16 * mi + g;
                int r2 = r1 + 8;
                const float* v = cacc[mi][nj];
                a_act[r1 * EPI_S + c0]     = q0 / (1.0f + __expf(-(v[0] + p0)));
                a_act[r1 * EPI_S + c0 + 1] = q1 / (1.0f + __expf(-(v[1] + p1)));
                a_act[r2 * EPI_S + c0]     = q0 / (1.0f + __expf(-(v[2] + p0)));
                a_act[r2 * EPI_S + c0 + 1] = q1 / (1.0f + __expf(-(v[3] + p1)));
            }
        }
    }
    if (t < NB) seg_part[t] = 0.0f;
    __syncthreads();

    // -------- phase 2: b-warps fuse tanh, multiply, reduce ------------------
    if (!is_a) {
        int slot = (warp_n - L) >> 6;   // 0 or 1
        float s[2][2] = {{0.f, 0.f}, {0.f, 0.f}};
#pragma unroll
        for (int nj = 0; nj < 8; nj++) {
            int l0 = (warp_n - L) + 8 * nj + 2 * tg;
            float p0 = bb[l0], p1 = bb[l0 + 1];
#pragma unroll
            for (int mi = 0; mi < 2; mi++) {
                int r1 = warp_m + 16 * mi + g;
                int r2 = r1 + 8;
                const float* v = cacc[mi][nj];
                s[mi][0] += tanhf(v[0] + p0) * a_act[r1 * EPI_S + l0]
                          + tanhf(v[1] + p1) * a_act[r1 * EPI_S + l0 + 1];
                s[mi][1] += tanhf(v[2] + p0) * a_act[r2 * EPI_S + l0]
                          + tanhf(v[3] + p1) * a_act[r2 * EPI_S + l0 + 1];
            }
        }
#pragma unroll
        for (int mi = 0; mi < 2; mi++)
#pragma unroll
            for (int q = 0; q < 2; q++) {
                s[mi][q] += __shfl_xor_sync(0xFFFFFFFFu, s[mi][q], 1);
                s[mi][q] += __shfl_xor_sync(0xFFFFFFFFu, s[mi][q], 2);
            }
        if (tg == 0) {
#pragma unroll
            for (int mi = 0; mi < 2; mi++) {
                int r1 = warp_m + 16 * mi + g;
                score_s[r1 * 2 + slot]       = s[mi][0];
                score_s[(r1 + 8) * 2 + slot] = s[mi][1];
            }
        }
    }
    __syncthreads();

    // -------- score write + per-segment exp-sum --------
    if (t < BM) {
        int row = r0 + t;
        if (row < n) {
            float sv = score_s[t * 2] + score_s[t * 2 + 1] + bc[0];
            score[row] = sv;
            atomicAdd(&seg_part[g_batch32[row]], __expf(sv));
        }
    }
    __syncthreads();
    if (t < NB && seg_part[t] != 0.0f) atomicAdd(&g_segsum[t], seg_part[t]);
}

// ---------------- final: softmax + weighted segment reduce + feature copy ---
__global__ __launch_bounds__(256)
void k_final(const float* __restrict__ feat,
             const float* __restrict__ score,
             float* __restrict__ softmax_out,
             float* __restrict__ featcopy,
             float* __restrict__ out_acc, int n)
{
    __shared__ float w_s[FBM];
    __shared__ int   seg_s[FBM];
    const int t  = threadIdx.x;
    const int r0 = blockIdx.x * FBM;

    if (t < FBM) {
        int row = r0 + t;
        if (row < n) {
            int b = g_batch32[row];
            float w = __expf(score[row]) / (g_segsum[b] + 1e-16f);
            w_s[t] = w; seg_s[t] = b;
            softmax_out[row] = w;
        } else {
            w_s[t] = 0.0f; seg_s[t] = -1;
        }
    }
    __syncthreads();

    const int c = t * 4;
    float4 acc = make_float4(0.f, 0.f, 0.f, 0.f);
    int cur = seg_s[0];
    int rows = n - r0; if (rows > FBM) rows = FBM;

    for (int r = 0; r < rows; r++) {
        int sg = seg_s[r];
        if (sg != cur) {
            float* dst = out_acc + (size_t)cur * D + c;
            atomicAdd(dst + 0, acc.x); atomicAdd(dst + 1, acc.y);
            atomicAdd(dst + 2, acc.z); atomicAdd(dst + 3, acc.w);
            acc = make_float4(0.f, 0.f, 0.f, 0.f);
            cur = sg;
        }
        size_t off = (size_t)(r0 + r) * D + c;
        float4 f = *reinterpret_cast<const float4*>(feat + off);
        *reinterpret_cast<float4*>(featcopy + off) = f;
        float w = w_s[r];
        acc.x = fmaf(w, f.x, acc.x); acc.y = fmaf(w, f.y, acc.y);
        acc.z = fmaf(w, f.z, acc.z); acc.w = fmaf(w, f.w, acc.w);
    }
    if (cur >= 0) {
        float* dst = out_acc + (size_t)cur * D + c;
        atomicAdd(dst + 0, acc.x); atomicAdd(dst + 1, acc.y);
        atomicAdd(dst + 2, acc.z); atomicAdd(dst + 3, acc.w);
    }
}

// ---------------- launch ----------------------------------------------------
extern "C" void kernel_launch(void* const* d_in, const int* in_sizes, int n_in,
                              void* d_out, int out_size)
{
    const float* feat  = (const float*)d_in[0];
    const void*  batch = d_in[1];
    const float* Wa    = (const float*)d_in[2];
    const float* ba    = (const float*)d_in[3];
    const float* Wb    = (const float*)d_in[4];
    const float* bb    = (const float*)d_in[5];
    const float* Wc    = (const float*)d_in[6];
    const float* bc    = (const float*)d_in[7];
    const int n = in_sizes[1];

    float* out      = (float*)d_out;           // [16, 1024]
    float* score    = out + NB * D;            // [N]
    float* softmax  = score + n;               // [N]
    float* featcopy = softmax + n;             // [N, 1024]

    const int gb  = (n + BM - 1) / BM;
    const int gbf = (n + FBM - 1) / FBM;
    const int dsmem = STAGES * (BM + NC) * KC * (int)sizeof(float); // 147456

    static int configured = -1;
    if (configured < 0) {
        cudaFuncSetAttribute(k_gemm_mma,
                             cudaFuncAttributeMaxDynamicSharedMemorySize, dsmem);
        configured = 1;
    }

    k_detect<<<1, 128>>>((const unsigned*)batch, n);
    k_convert<<<(n + 255) / 256, 256>>>(batch, n);
    k_init<<<64, 256>>>(out);
    k_gemm_mma<<<gb, 512, dsmem>>>(feat, Wa, ba, Wb, bb, Wc, bc, score, n);
    k_final<<<gbf, 256>>>(feat, score, softmax, featcopy, out, n);
}

// round 12
// speedup vs baseline: 1.4428x; 1.4428x over previous
#include <cuda_runtime.h>
#include <math.h>
#include <stdint.h>

#define D      1024
#define L      128
#define NB     16      // number of segments (B)
#define NC     256     // logit columns: 128 (a) + 128 (b)
#define BM     128     // rows per GEMM block tile
#define KC     32      // K-chunk (floats)
#define NK     (D / KC)        // 32
#define STAGES 3
#define NMAX   131072
#define FBM    64      // rows per block in k_final
#define EPI_S  132     // epilogue smem stride

// ---------------- device scratch (no allocations allowed) ----------------
__device__ float    g_segsum[NB];
__device__ int      g_is64;
__device__ int      g_batch32[NMAX];

__device__ __forceinline__ uint32_t smem_u32(const void* p) {
    return (uint32_t)__cvta_generic_to_shared(p);
}
__device__ __forceinline__ void cp16(uint32_t dst, const void* src, int sz) {
    asm volatile("cp.async.cg.shared.global [%0], [%1], 16, %2;"
                 :: "r"(dst), "l"(src), "r"(sz));
}
__device__ __forceinline__ void mma_tf32(float* c, const uint32_t* a,
                                         uint32_t b0, uint32_t b1) {
    asm volatile("mma.sync.aligned.m16n8k8.row.col.f32.tf32.tf32.f32 "
                 "{%0,%1,%2,%3}, {%4,%5,%6,%7}, {%8,%9}, {%0,%1,%2,%3};"
                 : "+f"(c[0]), "+f"(c[1]), "+f"(c[2]), "+f"(c[3])
                 : "r"(a[0]), "r"(a[1]), "r"(a[2]), "r"(a[3]),
                   "r"(b0), "r"(b1));
}
// XOR-chunk swizzle for 32-float rows: phys = r*32 + ((k/4 ^ (r&7))*4) + k%4
__device__ __forceinline__ int swz(int r, int k) {
    return r * KC + ((((k >> 2) ^ (r & 7)) & 7) << 2) + (k & 3);
}

// ---------------- batch dtype detection + canonicalization ---------------
__global__ void k_detect(const unsigned* __restrict__ words, int n) {
    __shared__ int zeros;
    if (threadIdx.x == 0) zeros = 0;
    __syncthreads();
    int start = (n > 128) ? (n - 128) : 0;
    for (int j = start + threadIdx.x; j < n; j += blockDim.x)
        if ((j & 1) && words[j] == 0u) atomicAdd(&zeros, 1);
    __syncthreads();
    if (threadIdx.x == 0) g_is64 = (zeros > 32) ? 1 : 0;
}
__global__ void k_convert(const void* __restrict__ b, int n) {
    int i = blockIdx.x * blockDim.x + threadIdx.x;
    if (i >= n) return;
    if (g_is64) g_batch32[i] = (int)((const long long*)b)[i];
    else        g_batch32[i] = ((const int*)b)[i];
}
__global__ void k_init(float* __restrict__ out_acc) {
    int i = blockIdx.x * blockDim.x + threadIdx.x;
    int stride = gridDim.x * blockDim.x;
    for (int j = i; j < NB * D; j += stride) out_acc[j] = 0.0f;
    if (i < NB) g_segsum[i] = 0.0f;
}

// ---------------- TF32 tensor-core GEMM + fused epilogue -------------------
// block tile: 128 rows x 256 cols, 512 threads, warp grid 4(m) x 4(n),
// warp tile 32x64. 3-stage cp.async pipeline, KC=32 (R4-measured config).
// Epilogue accumulates per-segment sum of exp(score) into g_segsum
// (unshifted softmax; |score| <= sum|Wc| ~ 13, well inside fp32).
__global__ __launch_bounds__(512, 1)
void k_gemm_mma(const float* __restrict__ feat,
                const float* __restrict__ Wa, const float* __restrict__ ba,
                const float* __restrict__ Wb, const float* __restrict__ bb,
                const float* __restrict__ Wc, const float* __restrict__ bc,
                float* __restrict__ score, int n)
{
    extern __shared__ float sm[];
    float* As_base = sm;                           // [STAGES][BM*KC]
    float* Bs_base = sm + STAGES * BM * KC;        // [STAGES][NC*KC]
    float* a_act   = sm;                           // epilogue reuse [BM][EPI_S]
    float* score_s = sm + BM * EPI_S;              // [BM][2]
    __shared__ float seg_part[NB];

    const int t      = threadIdx.x;
    const int lane   = t & 31;
    const int wid    = t >> 5;
    const int g      = lane >> 2;
    const int tg     = lane & 3;
    const int warp_m = (wid & 3) * 32;
    const int warp_n = (wid >> 2) * 64;
    const int r0     = blockIdx.x * BM;

    float cacc[2][8][4];
#pragma unroll
    for (int i = 0; i < 2; i++)
#pragma unroll
        for (int j = 0; j < 8; j++)
#pragma unroll
            for (int q = 0; q < 4; q++) cacc[i][j][q] = 0.0f;

    // -------- loader precompute (8 threads cover one 32-float row) ---------
    uint32_t a_dst[2]; const float* a_src[2]; int a_sz[2];
#pragma unroll
    for (int i = 0; i < 2; i++) {
        int id = t + 512 * i;
        int ar = id >> 3, ac = id & 7;
        int row = r0 + ar;
        int safe = (row < n) ? row : (n - 1);
        a_src[i] = feat + (size_t)safe * D + 4 * ac;
        a_sz[i]  = (row < n) ? 16 : 0;
        a_dst[i] = smem_u32(As_base + ar * KC + (((ac ^ (ar & 7)) & 7) << 2));
    }
    uint32_t b_dst[4]; const float* b_src[4];
#pragma unroll
    for (int i = 0; i < 4; i++) {
        int id = t + 512 * i;
        int nr = id >> 3, c = id & 7;
        b_src[i] = ((nr < L) ? (Wa + (size_t)nr * D)
                             : (Wb + (size_t)(nr - L) * D)) + 4 * c;
        b_dst[i] = smem_u32(Bs_base + nr * KC + (((c ^ (nr & 7)) & 7) << 2));
    }

    auto load_stage = [&](int slot, int kc) {
        uint32_t soA = (uint32_t)(slot * BM * KC * 4);
        uint32_t soB = (uint32_t)(slot * NC * KC * 4);
#pragma unroll
        for (int i = 0; i < 2; i++) cp16(a_dst[i] + soA, a_src[i] + kc, a_sz[i]);
#pragma unroll
        for (int i = 0; i < 4; i++) cp16(b_dst[i] + soB, b_src[i] + kc, 16);
    };

    auto compute_stage = [&](int slot) {
        const float* As = As_base + slot * (BM * KC);
        const float* Bs = Bs_base + slot * (NC * KC);
#pragma unroll
        for (int ks = 0; ks < 4; ks++) {
            const int k0 = 8 * ks;
            uint32_t af[2][4];
#pragma unroll
            for (int mi = 0; mi < 2; mi++) {
                int r1 = warp_m + 16 * mi + g;
                af[mi][0] = __float_as_uint(As[swz(r1,     k0 + tg)]);
                af[mi][1] = __float_as_uint(As[swz(r1 + 8, k0 + tg)]);
                af[mi][2] = __float_as_uint(As[swz(r1,     k0 + 4 + tg)]);
                af[mi][3] = __float_as_uint(As[swz(r1 + 8, k0 + 4 + tg)]);
            }
#pragma unroll
            for (int nj = 0; nj < 8; nj++) {
                int nr = warp_n + 8 * nj + g;
                uint32_t b0 = __float_as_uint(Bs[swz(nr, k0 + tg)]);
                uint32_t b1 = __float_as_uint(Bs[swz(nr, k0 + 4 + tg)]);
                mma_tf32(cacc[0][nj], af[0], b0, b1);
                mma_tf32(cacc[1][nj], af[1], b0, b1);
            }
        }
    };

    // -------- 3-stage pipeline --------
#pragma unroll
    for (int s = 0; s < STAGES - 1; s++) {
        load_stage(s, s * KC);
        asm volatile("cp.async.commit_group;" ::: "memory");
    }
    for (int ki = 0; ki < NK; ki++) {
        asm volatile("cp.async.wait_group 1;" ::: "memory");
        __syncthreads();                       // data ki visible; ki-1 compute done
        int kn = ki + STAGES - 1;
        if (kn < NK) load_stage(kn % STAGES, kn * KC);
        asm volatile("cp.async.commit_group;" ::: "memory");
        compute_stage(ki % STAGES);
    }
    asm volatile("cp.async.wait_group 0;" ::: "memory");
    __syncthreads();   // all compute done; smem now reusable for epilogue

    // -------- epilogue phase 1: a-warps stage Wc*sigmoid into smem ----------
    const bool is_a = (warp_n < L);
    if (is_a) {
#pragma unroll
        for (int nj = 0; nj < 8; nj++) {
            int c0 = warp_n + 8 * nj + 2 * tg;
            float p0 = ba[c0], p1 = ba[c0 + 1];
            float q0 = Wc[c0], q1 = Wc[c0 + 1];
#pragma unroll
            for (int mi = 0; mi < 2; mi++) {
                int r1 = warp_m + 16 * mi + g;
                int r2 = r1 + 8;
                const float* v = cacc[mi][nj];
                a_act[r1 * EPI_S + c0]     = q0 / (1.0f + __expf(-(v[0] + p0)));
                a_act[r1 * EPI_S + c0 + 1] = q1 / (1.0f + __expf(-(v[1] + p1)));
                a_act[r2 * EPI_S + c0]     = q0 / (1.0f + __expf(-(v[2] + p0)));
                a_act[r2 * EPI_S + c0 + 1] = q1 / (1.0f + __expf(-(v[3] + p1)));
            }
        }
    }
    if (t < NB) seg_part[t] = 0.0f;
    __syncthreads();

    // -------- phase 2: b-warps fuse tanh, multiply, reduce ------------------
    if (!is_a) {
        int slot = (warp_n - L) >> 6;   // 0 or 1
        float s[2][2] = {{0.f, 0.f}, {0.f, 0.f}};
#pragma unroll
        for (int nj = 0; nj < 8; nj++) {
            int l0 = (warp_n - L) + 8 * nj + 2 * tg;
            float p0 = bb[l0], p1 = bb[l0 + 1];
#pragma unroll
            for (int mi = 0; mi < 2; mi++) {
                int r1 = warp_m + 16 * mi + g;
                int r2 = r1 + 8;
                const float* v = cacc[mi][nj];
                s[mi][0] += tanhf(v[0] + p0) * a_act[r1 * EPI_S + l0]
                          + tanhf(v[1] + p1) * a_act[r1 * EPI_S + l0 + 1];
                s[mi][1] += tanhf(v[2] + p0) * a_act[r2 * EPI_S + l0]
                          + tanhf(v[3] + p1) * a_act[r2 * EPI_S + l0 + 1];
            }
        }
#pragma unroll
        for (int mi = 0; mi < 2; mi++)
#pragma unroll
            for (int q = 0; q < 2; q++) {
                s[mi][q] += __shfl_xor_sync(0xFFFFFFFFu, s[mi][q], 1);
                s[mi][q] += __shfl_xor_sync(0xFFFFFFFFu, s[mi][q], 2);
            }
        if (tg == 0) {
#pragma unroll
            for (int mi = 0; mi < 2; mi++) {
                int r1 = warp_m + 16 * mi + g;
                score_s[r1 * 2 + slot]       = s[mi][0];
                score_s[(r1 + 8) * 2 + slot] = s[mi][1];
            }
        }
    }
    __syncthreads();

    // -------- score write + per-segment exp-sum --------
    if (t < BM) {
        int row = r0 + t;
        if (row < n) {
            float sv = score_s[t * 2] + score_s[t * 2 + 1] + bc[0];
            score[row] = sv;
            atomicAdd(&seg_part[g_batch32[row]], __expf(sv));
        }
    }
    __syncthreads();
    if (t < NB && seg_part[t] != 0.0f) atomicAdd(&g_segsum[t], seg_part[t]);
}

// ---------------- final: softmax + weighted segment reduce + feature copy ---
__global__ __launch_bounds__(256)
void k_final(const float* __restrict__ feat,
             const float* __restrict__ score,
             float* __restrict__ softmax_out,
             float* __restrict__ featcopy,
             float* __restrict__ out_acc, int n)
{
    __shared__ float w_s[FBM];
    __shared__ int   seg_s[FBM];
    const int t  = threadIdx.x;
    const int r0 = blockIdx.x * FBM;

    if (t < FBM) {
        int row = r0 + t;
        if (row < n) {
            int b = g_batch32[row];
            float w = __expf(score[row]) / (g_segsum[b] + 1e-16f);
            w_s[t] = w; seg_s[t] = b;
            __stcs(softmax_out + row, w);         // streaming: no reuse
        } else {
            w_s[t] = 0.0f; seg_s[t] = -1;
        }
    }
    __syncthreads();

    const int c = t * 4;
    float4 acc = make_float4(0.f, 0.f, 0.f, 0.f);
    int cur = seg_s[0];
    int rows = n - r0; if (rows > FBM) rows = FBM;

    for (int r = 0; r < rows; r++) {
        int sg = seg_s[r];
        if (sg != cur) {
            float* dst = out_acc + (size_t)cur * D + c;
            atomicAdd(dst + 0, acc.x); atomicAdd(dst + 1, acc.y);
            atomicAdd(dst + 2, acc.z); atomicAdd(dst + 3, acc.w);
            acc = make_float4(0.f, 0.f, 0.f, 0.f);
            cur = sg;
        }
        size_t off = (size_t)(r0 + r) * D + c;
        float4 f = __ldcs(reinterpret_cast<const float4*>(feat + off));
        __stcs(reinterpret_cast<float4*>(featcopy + off), f);   // streaming copy
        float w = w_s[r];
        acc.x = fmaf(w, f.x, acc.x); acc.y = fmaf(w, f.y, acc.y);
        acc.z = fmaf(w, f.z, acc.z); acc.w = fmaf(w, f.w, acc.w);
    }
    if (cur >= 0) {
        float* dst = out_acc + (size_t)cur * D + c;
        atomicAdd(dst + 0, acc.x); atomicAdd(dst + 1, acc.y);
        atomicAdd(dst + 2, acc.z); atomicAdd(dst + 3, acc.w);
    }
}

// ---------------- launch ----------------------------------------------------
extern "C" void kernel_launch(void* const* d_in, const int* in_sizes, int n_in,
                              void* d_out, int out_size)
{
    const float* feat  = (const float*)d_in[0];
    const void*  batch = d_in[1];
    const float* Wa    = (const float*)d_in[2];
    const float* ba    = (const float*)d_in[3];
    const float* Wb    = (const float*)d_in[4];
    const float* bb    = (const float*)d_in[5];
    const float* Wc    = (const float*)d_in[6];
    const float* bc    = (const float*)d_in[7];
    const int n = in_sizes[1];

    float* out      = (float*)d_out;           // [16, 1024]
    float* score    = out + NB * D;            // [N]
    float* softmax  = score + n;               // [N]
    float* featcopy = softmax + n;             // [N, 1024]

    const int gb  = (n + BM - 1) / BM;
    const int gbf = (n + FBM - 1) / FBM;
    const int dsmem = STAGES * (BM + NC) * KC * (int)sizeof(float); // 147456

    static int configured = -1;
    if (configured < 0) {
        cudaFuncSetAttribute(k_gemm_mma,
                             cudaFuncAttributeMaxDynamicSharedMemorySize, dsmem);
        configured = 1;
    }

    k_detect<<<1, 128>>>((const unsigned*)batch, n);
    k_convert<<<(n + 255) / 256, 256>>>(batch, n);
    k_init<<<64, 256>>>(out);
    k_gemm_mma<<<gb, 512, dsmem>>>(feat, Wa, ba, Wb, bb, Wc, bc, score, n);
    k_final<<<gbf, 256>>>(feat, score, softmax, featcopy, out, n);
}